// round 14
// baseline (speedup 1.0000x reference)
#include <cuda_runtime.h>
#include <cuda_fp16.h>
#include <cstdint>

// Problem constants
#define NROWS 65536
#define DDIM  1024
#define KC    256

// ---------------- device scratch (no allocations allowed) ----------------
__device__ __half g_xh[(size_t)NROWS * DDIM];  // rn-fp16 x
__device__ __half g_Uh[(size_t)NROWS * KC];    // rn-fp16 U
__device__ float  g_V[(size_t)NROWS * KC];
__device__ float  g_Z[(size_t)NROWS * KC];
__device__ __half g_Wh[(size_t)DDIM * DDIM];   // rn-fp16 W
__device__ __half g_Hh[KC * KC];               // rn-fp16 H/256
__device__ float  g_Hpart[128 * KC * KC];      // 128 n-splits of H = Z^T V
__device__ float  g_cspU[256 * KC];
__device__ float  g_cspV[256 * KC];
__device__ float  g_pdot[KC];
__device__ float  g_D;

// ---------------- helpers ----------------
__device__ __forceinline__ unsigned f2tf(float f) {
    unsigned u;
    asm("cvt.rna.tf32.f32 %0, %1;" : "=r"(u) : "f"(f));
    return u;
}
__device__ __forceinline__ float f2tf_f(float f) { return __uint_as_float(f2tf(f)); }
// pack two f32 -> f16x2 (lo = first element, hi = second)
__device__ __forceinline__ unsigned pack_h2(float lo, float hi) {
    unsigned d;
    asm("cvt.rn.f16x2.f32 %0, %1, %2;" : "=r"(d) : "f"(hi), "f"(lo));
    return d;
}
__device__ __forceinline__ unsigned s2u(const void* p) {
    return (unsigned)__cvta_generic_to_shared(p);
}
__device__ __forceinline__ void cpa16(void* s, const void* g) {
    asm volatile("cp.async.cg.shared.global [%0], [%1], 16;" :: "r"(s2u(s)), "l"(g));
}
__device__ __forceinline__ void cpcommit() { asm volatile("cp.async.commit_group;"); }
template <int N> __device__ __forceinline__ void cpwait() {
    asm volatile("cp.async.wait_group %0;" :: "n"(N));
}
__device__ __forceinline__ void ldsm4(unsigned* r, unsigned a) {
    asm volatile("ldmatrix.sync.aligned.m8n8.x4.shared.b16 {%0,%1,%2,%3}, [%4];"
                 : "=r"(r[0]), "=r"(r[1]), "=r"(r[2]), "=r"(r[3]) : "r"(a));
}
__device__ __forceinline__ void mma16(float* c, const unsigned* a, const unsigned* b) {
    asm volatile(
        "mma.sync.aligned.m16n8k16.row.col.f32.f16.f16.f32 "
        "{%0,%1,%2,%3},{%4,%5,%6,%7},{%8,%9},{%0,%1,%2,%3};"
        : "+f"(c[0]), "+f"(c[1]), "+f"(c[2]), "+f"(c[3])
        : "r"(a[0]), "r"(a[1]), "r"(a[2]), "r"(a[3]), "r"(b[0]), "r"(b[1]));
}
__device__ __forceinline__ void mma8(float* c, const unsigned* a, const unsigned* b) {
    asm volatile(
        "mma.sync.aligned.m16n8k8.row.col.f32.tf32.tf32.f32 "
        "{%0,%1,%2,%3},{%4,%5,%6,%7},{%8,%9},{%0,%1,%2,%3};"
        : "+f"(c[0]), "+f"(c[1]), "+f"(c[2]), "+f"(c[3])
        : "r"(a[0]), "r"(a[1]), "r"(a[2]), "r"(a[3]), "r"(b[0]), "r"(b[1]));
}

// ---------------- prepasses ----------------
__global__ void xh_k(const float* __restrict__ x) {
    size_t i = ((size_t)blockIdx.x * 256 + threadIdx.x) * 4;
    float4 v = *(const float4*)(x + i);
    uint2 o;
    o.x = pack_h2(v.x, v.y);
    o.y = pack_h2(v.z, v.w);
    *(uint2*)((char*)g_xh + i * 2) = o;
}
__global__ void Wh_k(const float* __restrict__ W) {
    int i = (blockIdx.x * 256 + threadIdx.x) * 4;
    float4 v = *(const float4*)(W + i);
    uint2 o;
    o.x = pack_h2(v.x, v.y);
    o.y = pack_h2(v.z, v.w);
    *(uint2*)((char*)g_Wh + (size_t)i * 2) = o;
}
__global__ void dummy_k() {}

// ================= fp16 NT GEMM: C[M,N] = A[M,KA] * B[N,KA]^T =================
// CTA 256(M)x128(N), 8 warps (4x2), warp tile 64x64. K-chunk 64 (4 x K16 mma).
// A,B fp16 smem, row stride 144B (conflict-free ldmatrix), 3-stage cp.async,
// one __syncthreads per K-chunk, 1 CTA/SM (166KB smem, ~180 regs).
// B fragments: paired ldsm4 (two nt per instruction).
// EPI=0: bias+relu; bx 0..1 -> g_Uh (fp16), 2..5 -> V/Z (tf32-rounded fp32),
//        6..7 -> out[:,256:512].
// EPI=1: res = U * (H/256)^T * (g_D*256) -> out[:, 0:256].
template <int KA, int EPI>
__global__ __launch_bounds__(256, 1)
void gemm_h(const float* __restrict__ bias, float* __restrict__ out) {
    extern __shared__ unsigned smu[];
    const int RS = 36;                       // row stride in uints (144B)
    const int TILEA = 256 * RS;              // A tile, uints
    const int TILEB = 128 * RS;              // B tile, uints
    const int STu = TILEA + TILEB;           // stage size, uints

    const __half* A = (EPI == 1) ? g_Uh : g_xh;
    const __half* B = (EPI == 1) ? g_Hh : g_Wh;

    const int m0 = blockIdx.y * 256, n0 = blockIdx.x * 128;
    const int tid = threadIdx.x;
    const int warp = tid >> 5, lane = tid & 31, g = lane >> 2, tg = lane & 3;
    const int wm = (warp >> 1) * 64, wn = (warp & 1) * 64;

    float acc[4][8][4];
#pragma unroll
    for (int i = 0; i < 4; i++)
#pragma unroll
        for (int j = 0; j < 8; j++)
#pragma unroll
            for (int c = 0; c < 4; c++) acc[i][j][c] = 0.f;

    const int NK = KA / 64;

    auto load_stage = [&](int s) {
        unsigned* sA = smu + (s % 3) * STu;
        unsigned* sB = sA + TILEA;
        const int k0 = s * 64;
#pragma unroll
        for (int i = 0; i < 8; i++) {        // A: 256 rows x 64 halfs (8x16B/row)
            int idx = tid + i * 256;
            int row = idx >> 3, q = idx & 7;
            cpa16(sA + row * RS + q * 4, A + (size_t)(m0 + row) * KA + k0 + q * 8);
        }
#pragma unroll
        for (int i = 0; i < 4; i++) {        // B: 128 rows x 64 halfs
            int idx = tid + i * 256;
            int row = idx >> 3, q = idx & 7;
            cpa16(sB + row * RS + q * 4, B + (size_t)(n0 + row) * KA + k0 + q * 8);
        }
        cpcommit();
    };

    // ldmatrix per-thread address components
    const int a_row = lane & 15;               // m row within 16
    const int a_koff = ((lane >> 4) & 1) * 16; // k half (bytes)
    const int b_row = lane & 7;                // n row within 8
    const int b_blk = (lane >> 4) & 1;         // which nt of the pair
    const int b_koff = ((lane >> 3) & 1) * 16; // k half (bytes)

    load_stage(0);
    load_stage(1);

    for (int kt = 0; kt < NK; kt++) {
        if (kt + 1 < NK) cpwait<1>(); else cpwait<0>();
        __syncthreads();
        // buffer (kt+2)%3 was last read in iter kt-1; readers passed the barrier.
        if (kt + 2 < NK) load_stage(kt + 2);

        const unsigned aA = s2u(smu + (kt % 3) * STu);
        const unsigned aB = aA + TILEA * 4;

#pragma unroll
        for (int kk = 0; kk < 4; kk++) {     // 4 x K16 per K64 chunk
            unsigned af[4][4], bf[8][2];
#pragma unroll
            for (int mt = 0; mt < 4; mt++)
                ldsm4(af[mt], aA + (unsigned)((wm + mt * 16 + a_row) * 144 + kk * 32 + a_koff));
#pragma unroll
            for (int np = 0; np < 4; np++) {
                unsigned r[4];
                ldsm4(r, aB + (unsigned)((wn + (np * 2 + b_blk) * 8 + b_row) * 144 + kk * 32 + b_koff));
                bf[np * 2][0] = r[0]; bf[np * 2][1] = r[1];
                bf[np * 2 + 1][0] = r[2]; bf[np * 2 + 1][1] = r[3];
            }
#pragma unroll
            for (int mt = 0; mt < 4; mt++)
#pragma unroll
                for (int nt = 0; nt < 8; nt++)
                    mma16(acc[mt][nt], af[mt], bf[nt]);
        }
    }

    // ---------------- epilogue ----------------
    const float Dscale = (EPI == 1) ? g_D * 256.f : 1.f;
#pragma unroll
    for (int mt = 0; mt < 4; mt++) {
#pragma unroll
        for (int nt = 0; nt < 8; nt++) {
            int cl = wn + nt * 8 + tg * 2;          // col in [0,128)
            int r0 = wm + mt * 16 + g;              // rows r0, r0+8
            float2 v01 = make_float2(acc[mt][nt][0], acc[mt][nt][1]);
            float2 v23 = make_float2(acc[mt][nt][2], acc[mt][nt][3]);
            if (EPI == 0) {
                float2 bb = *(const float2*)(bias + n0 + cl);
                v01.x = fmaxf(v01.x + bb.x, 0.f); v01.y = fmaxf(v01.y + bb.y, 0.f);
                v23.x = fmaxf(v23.x + bb.x, 0.f); v23.y = fmaxf(v23.y + bb.y, 0.f);
                int bx = blockIdx.x;                // 8 n-blocks of 128
                int lc = (bx & 1) * 128 + cl;       // col within 256-seg
                if (bx < 2) {                       // U -> fp16 (GEMM3 operand)
                    *(unsigned*)((char*)g_Uh + ((size_t)(m0 + r0) * KC + lc) * 2) =
                        pack_h2(v01.x, v01.y);
                    *(unsigned*)((char*)g_Uh + ((size_t)(m0 + r0 + 8) * KC + lc) * 2) =
                        pack_h2(v23.x, v23.y);
                } else if (bx < 6) {                // V/Z: tf32-rounded for gemm_tn
                    v01.x = f2tf_f(v01.x); v01.y = f2tf_f(v01.y);
                    v23.x = f2tf_f(v23.x); v23.y = f2tf_f(v23.y);
                    float* dst = (bx < 4) ? g_V : g_Z;
                    *(float2*)(dst + (size_t)(m0 + r0) * KC + lc) = v01;
                    *(float2*)(dst + (size_t)(m0 + r0 + 8) * KC + lc) = v23;
                } else {
                    *(float2*)(out + (size_t)(m0 + r0) * 512 + 256 + lc) = v01;
                    *(float2*)(out + (size_t)(m0 + r0 + 8) * 512 + 256 + lc) = v23;
                }
            } else {
                v01.x *= Dscale; v01.y *= Dscale; v23.x *= Dscale; v23.y *= Dscale;
                int gc = n0 + cl;
                *(float2*)(out + (size_t)(m0 + r0) * 512 + gc) = v01;
                *(float2*)(out + (size_t)(m0 + r0 + 8) * 512 + gc) = v23;
            }
        }
    }
}

// ---------------- H partials (tf32): Hpart[z][j][k] = sum_nchunk Z[n,j]*V[n,k] ----------------
// 128 n-splits of 512 rows each.
__global__ __launch_bounds__(256)
void gemm_tn() {
    extern __shared__ float sm[];
    const int TS = 32 * 132;
    float* sZ[2] = { sm, sm + TS };
    float* sV[2] = { sm + 2 * TS, sm + 3 * TS };

    int k0 = blockIdx.x * 128;
    int j0 = blockIdx.y * 128;
    int nb = blockIdx.z * 512;
    int tid = threadIdx.x;
    int warp = tid >> 5, lane = tid & 31, g = lane >> 2, tg = lane & 3;
    int wm = (warp >> 2) * 64, wn = (warp & 3) * 32;

    float acc[4][4][4];
#pragma unroll
    for (int i = 0; i < 4; i++)
#pragma unroll
        for (int j = 0; j < 4; j++)
#pragma unroll
            for (int c = 0; c < 4; c++) acc[i][j][c] = 0.f;

    auto load_stage = [&](int s, int it) {
        int r0 = nb + it * 32;
#pragma unroll
        for (int i = 0; i < 4; i++) {
            int vi = tid + i * 256;
            int row = vi >> 5, cv = (vi & 31) * 4;
            cpa16(sZ[s] + row * 132 + cv, g_Z + (size_t)(r0 + row) * KC + j0 + cv);
            cpa16(sV[s] + row * 132 + cv, g_V + (size_t)(r0 + row) * KC + k0 + cv);
        }
        cpcommit();
    };

    const int NK = 16;  // 512 rows / 32
    load_stage(0, 0);
    int buf = 0;
    for (int kt = 0; kt < NK; kt++) {
        if (kt + 1 < NK) { load_stage(buf ^ 1, kt + 1); cpwait<1>(); }
        else             { cpwait<0>(); }
        __syncthreads();
        const float* cZ = sZ[buf];
        const float* cV = sV[buf];
#pragma unroll
        for (int kk = 0; kk < 4; kk++) {
            int kb = kk * 8 + tg;
            unsigned af[4][4], bf[4][2];
#pragma unroll
            for (int mt2 = 0; mt2 < 4; mt2++) {
                const float* p = cZ + kb * 132 + wm + mt2 * 16 + g;
                af[mt2][0] = __float_as_uint(p[0]);
                af[mt2][1] = __float_as_uint(p[8]);
                af[mt2][2] = __float_as_uint(p[4 * 132]);
                af[mt2][3] = __float_as_uint(p[4 * 132 + 8]);
            }
#pragma unroll
            for (int nt = 0; nt < 4; nt++) {
                const float* p = cV + kb * 132 + wn + nt * 8 + g;
                bf[nt][0] = __float_as_uint(p[0]);
                bf[nt][1] = __float_as_uint(p[4 * 132]);
            }
#pragma unroll
            for (int mt2 = 0; mt2 < 4; mt2++)
#pragma unroll
                for (int nt = 0; nt < 4; nt++)
                    mma8(acc[mt2][nt], af[mt2], bf[nt]);
        }
        __syncthreads();
        buf ^= 1;
    }

    float* dst = g_Hpart + (size_t)blockIdx.z * (KC * KC);
#pragma unroll
    for (int mt2 = 0; mt2 < 4; mt2++)
#pragma unroll
        for (int nt = 0; nt < 4; nt++)
#pragma unroll
            for (int c = 0; c < 4; c++) {
                int rl = wm + mt2 * 16 + g + ((c >= 2) ? 8 : 0);
                int cl = wn + nt * 8 + tg * 2 + (c & 1);
                dst[(j0 + rl) * KC + (k0 + cl)] = acc[mt2][nt][c];
            }
}

// ---------------- column-sum partials (U fp16, V fp32) ----------------
__global__ void colsum_k() {
    int j = threadIdx.x;
    int r0 = blockIdx.x * 256;
    float s = 0.f;
    if (blockIdx.y == 0) {
        for (int r = 0; r < 256; r++) s += __half2float(g_Uh[(size_t)(r0 + r) * KC + j]);
        g_cspU[blockIdx.x * KC + j] = s;
    } else {
        for (int r = 0; r < 256; r++) s += g_V[(size_t)(r0 + r) * KC + j];
        g_cspV[blockIdx.x * KC + j] = s;
    }
}

// ---------------- per-column dot partial: pdot[j] = su_j * sv_j ----------------
__global__ void sumpart_k() {
    int j = blockIdx.x;
    int t = threadIdx.x;
    float u = g_cspU[t * KC + j];
    float v = g_cspV[t * KC + j];
#pragma unroll
    for (int o = 16; o > 0; o >>= 1) {
        u += __shfl_xor_sync(0xffffffffu, u, o);
        v += __shfl_xor_sync(0xffffffffu, v, o);
    }
    __shared__ float ru[8], rv[8];
    if ((t & 31) == 0) { ru[t >> 5] = u; rv[t >> 5] = v; }
    __syncthreads();
    if (t == 0) {
        float su = 0.f, sv = 0.f;
        for (int w = 0; w < 8; w++) { su += ru[w]; sv += rv[w]; }
        g_pdot[j] = su * sv;
    }
}

// ---------------- scalar D ----------------
__global__ void scalar_k() {
    int t = threadIdx.x;
    float p = g_pdot[t * 8] + g_pdot[t * 8 + 1] + g_pdot[t * 8 + 2] + g_pdot[t * 8 + 3]
            + g_pdot[t * 8 + 4] + g_pdot[t * 8 + 5] + g_pdot[t * 8 + 6] + g_pdot[t * 8 + 7];
#pragma unroll
    for (int o = 16; o > 0; o >>= 1) p += __shfl_xor_sync(0xffffffffu, p, o);
    if (t == 0) g_D = 1.f / (p / (float)NROWS + 1e-6f);
}

// ---------------- reduce H partials -> fp16 H/256 ----------------
__global__ void reduceH_k() {
    int i = blockIdx.x * 256 + threadIdx.x;
    float s = 0.f;
    for (int p = 0; p < 128; p++) s += g_Hpart[(size_t)p * (KC * KC) + i];
    g_Hh[i] = __float2half_rn(s * (1.f / 256.f));
}

// ---------------- launcher ----------------
extern "C" void kernel_launch(void* const* d_in, const int* in_sizes, int n_in,
                              void* d_out, int out_size) {
    const float* x = (const float*)d_in[0];
    const float* W = (const float*)d_in[1];
    const float* b = (const float*)d_in[2];
    float* out = (float*)d_out;

    const int SM_H  = 3 * (256 + 128) * 36 * 4;  // 165888 B -> 1 CTA/SM
    const int SM_TN = 4 * 32 * 132 * 4;          // 67584 B
    cudaFuncSetAttribute(gemm_h<1024, 0>, cudaFuncAttributeMaxDynamicSharedMemorySize, SM_H);
    cudaFuncSetAttribute(gemm_h<256, 1>,  cudaFuncAttributeMaxDynamicSharedMemorySize, SM_H);
    cudaFuncSetAttribute(gemm_tn,         cudaFuncAttributeMaxDynamicSharedMemorySize, SM_TN);

    // 0) prepasses + ncu alignment: gemm1 lands at global launch index 5 (-s 5)
    xh_k<<<NROWS * DDIM / 1024, 256>>>(x);
    Wh_k<<<1024, 256>>>(W);
    dummy_k<<<1, 32>>>();
    // 1) tmp = relu(x W^T + b): bx 0..1 -> Uh, 2..5 -> V/Z, 6..7 -> out[:,256:512]
    gemm_h<1024, 0><<<dim3(8, 256), 256, SM_H>>>(b, out);
    // 2) column sums of U and V (partials)
    colsum_k<<<dim3(256, 2), 256>>>();
    // 3) per-column dot partials
    sumpart_k<<<256, 256>>>();
    // 4) H = Z^T V partials over 128 n-splits (tf32)
    gemm_tn<<<dim3(2, 2, 128), 256, SM_TN>>>();
    // 5) D scalar
    scalar_k<<<1, 32>>>();
    // 6) reduce H partials -> fp16 H/256 (deterministic order)
    reduceH_k<<<256, 256>>>();
    // 7) res = U * (H/256)^T * (D*256) -> out[:,0:256]
    gemm_h<256, 1><<<dim3(2, 256), 256, SM_H>>>(nullptr, out);
}

// round 15
// speedup vs baseline: 1.1639x; 1.1639x over previous
#include <cuda_runtime.h>
#include <cuda_fp16.h>
#include <cstdint>

// Problem constants
#define NROWS 65536
#define DDIM  1024
#define KC    256

// ---------------- device scratch (no allocations allowed) ----------------
__device__ __half g_xh[(size_t)NROWS * DDIM];  // rn-fp16 x
__device__ __half g_Uh[(size_t)NROWS * KC];    // rn-fp16 U
__device__ __half g_Vh[(size_t)NROWS * KC];    // rn-fp16 V
__device__ __half g_Zh[(size_t)NROWS * KC];    // rn-fp16 Z
__device__ __half g_Wh[(size_t)DDIM * DDIM];   // rn-fp16 W
__device__ __half g_Hh[KC * KC];               // rn-fp16 H/256
__device__ float  g_Hpart[128 * KC * KC];      // 128 n-splits of H = Z^T V
__device__ float  g_cspU[256 * KC];
__device__ float  g_cspV[256 * KC];
__device__ float  g_pdot[KC];
__device__ float  g_D;

// ---------------- helpers ----------------
// pack two f32 -> f16x2 (lo = first element, hi = second)
__device__ __forceinline__ unsigned pack_h2(float lo, float hi) {
    unsigned d;
    asm("cvt.rn.f16x2.f32 %0, %1, %2;" : "=r"(d) : "f"(hi), "f"(lo));
    return d;
}
__device__ __forceinline__ unsigned s2u(const void* p) {
    return (unsigned)__cvta_generic_to_shared(p);
}
__device__ __forceinline__ void cpa16(void* s, const void* g) {
    asm volatile("cp.async.cg.shared.global [%0], [%1], 16;" :: "r"(s2u(s)), "l"(g));
}
__device__ __forceinline__ void cpcommit() { asm volatile("cp.async.commit_group;"); }
template <int N> __device__ __forceinline__ void cpwait() {
    asm volatile("cp.async.wait_group %0;" :: "n"(N));
}
__device__ __forceinline__ void ldsm4(unsigned* r, unsigned a) {
    asm volatile("ldmatrix.sync.aligned.m8n8.x4.shared.b16 {%0,%1,%2,%3}, [%4];"
                 : "=r"(r[0]), "=r"(r[1]), "=r"(r[2]), "=r"(r[3]) : "r"(a));
}
__device__ __forceinline__ void ldsm4t(unsigned* r, unsigned a) {
    asm volatile("ldmatrix.sync.aligned.m8n8.x4.trans.shared.b16 {%0,%1,%2,%3}, [%4];"
                 : "=r"(r[0]), "=r"(r[1]), "=r"(r[2]), "=r"(r[3]) : "r"(a));
}
__device__ __forceinline__ void ldsm2t(unsigned* r, unsigned a) {
    asm volatile("ldmatrix.sync.aligned.m8n8.x2.trans.shared.b16 {%0,%1}, [%2];"
                 : "=r"(r[0]), "=r"(r[1]) : "r"(a));
}
__device__ __forceinline__ void mma16(float* c, const unsigned* a, const unsigned* b) {
    asm volatile(
        "mma.sync.aligned.m16n8k16.row.col.f32.f16.f16.f32 "
        "{%0,%1,%2,%3},{%4,%5,%6,%7},{%8,%9},{%0,%1,%2,%3};"
        : "+f"(c[0]), "+f"(c[1]), "+f"(c[2]), "+f"(c[3])
        : "r"(a[0]), "r"(a[1]), "r"(a[2]), "r"(a[3]), "r"(b[0]), "r"(b[1]));
}

// ---------------- prepasses ----------------
__global__ void xh_k(const float* __restrict__ x) {
    size_t i = ((size_t)blockIdx.x * 256 + threadIdx.x) * 4;
    float4 v = *(const float4*)(x + i);
    uint2 o;
    o.x = pack_h2(v.x, v.y);
    o.y = pack_h2(v.z, v.w);
    *(uint2*)((char*)g_xh + i * 2) = o;
}
__global__ void Wh_k(const float* __restrict__ W) {
    int i = (blockIdx.x * 256 + threadIdx.x) * 4;
    float4 v = *(const float4*)(W + i);
    uint2 o;
    o.x = pack_h2(v.x, v.y);
    o.y = pack_h2(v.z, v.w);
    *(uint2*)((char*)g_Wh + (size_t)i * 2) = o;
}
__global__ void dummy_k() {}

// ================= fp16 NT GEMM: C[M,N] = A[M,KA] * B[N,KA]^T =================
// CTA 128x128, 4 warps (2x2), warp tile 64x64. K-chunk 64 (4 x K16 mma).
// A,B fp16 smem, 144B rows (conflict-free ldmatrix), 3-stage cp.async,
// one __syncthreads per K-chunk, 2 CTAs/SM (110.6KB smem, 128 threads).
// EPI=0: bias+relu; bx 0..5 -> g_Uh/g_Vh/g_Zh (fp16), bx 6..7 -> out[:,256:512].
// EPI=1: res = U * (H/256)^T * (g_D*256) -> out[:, 0:256].
template <int KA, int EPI>
__global__ __launch_bounds__(128, 2)
void gemm_h(const float* __restrict__ bias, float* __restrict__ out) {
    extern __shared__ unsigned smu[];
    const int RS = 36;                       // row stride in uints (144B)
    const int TILE = 128 * RS;               // one operand tile, uints
    const int STu = 2 * TILE;                // stage size, uints

    const __half* A = (EPI == 1) ? g_Uh : g_xh;
    const __half* B = (EPI == 1) ? g_Hh : g_Wh;

    const int m0 = blockIdx.y * 128, n0 = blockIdx.x * 128;
    const int tid = threadIdx.x;
    const int warp = tid >> 5, lane = tid & 31, g = lane >> 2, tg = lane & 3;
    const int wm = (warp >> 1) * 64, wn = (warp & 1) * 64;

    float acc[4][8][4];
#pragma unroll
    for (int i = 0; i < 4; i++)
#pragma unroll
        for (int j = 0; j < 8; j++)
#pragma unroll
            for (int c = 0; c < 4; c++) acc[i][j][c] = 0.f;

    const int NK = KA / 64;

    auto load_stage = [&](int s) {
        unsigned* sA = smu + (s % 3) * STu;
        unsigned* sB = sA + TILE;
        const int k0 = s * 64;
#pragma unroll
        for (int i = 0; i < 8; i++) {        // A: 128 rows x 64 halfs (8x16B/row)
            int idx = tid + i * 128;
            int row = idx >> 3, q = idx & 7;
            cpa16(sA + row * RS + q * 4, A + (size_t)(m0 + row) * KA + k0 + q * 8);
        }
#pragma unroll
        for (int i = 0; i < 8; i++) {        // B: 128 rows x 64 halfs
            int idx = tid + i * 128;
            int row = idx >> 3, q = idx & 7;
            cpa16(sB + row * RS + q * 4, B + (size_t)(n0 + row) * KA + k0 + q * 8);
        }
        cpcommit();
    };

    // ldmatrix per-thread address components
    const int a_row = lane & 15;               // m row within 16
    const int a_koff = ((lane >> 4) & 1) * 16; // k half (bytes)
    const int b_row = lane & 7;                // n row within 8
    const int b_blk = (lane >> 4) & 1;         // which nt of the pair
    const int b_koff = ((lane >> 3) & 1) * 16; // k half (bytes)

    load_stage(0);
    load_stage(1);

    for (int kt = 0; kt < NK; kt++) {
        if (kt + 1 < NK) cpwait<1>(); else cpwait<0>();
        __syncthreads();
        // buffer (kt+2)%3 was last read in iter kt-1; readers passed the barrier.
        if (kt + 2 < NK) load_stage(kt + 2);

        const unsigned aA = s2u(smu + (kt % 3) * STu);
        const unsigned aB = aA + TILE * 4;

#pragma unroll
        for (int kk = 0; kk < 4; kk++) {     // 4 x K16 per K64 chunk
            unsigned af[4][4], bf[8][2];
#pragma unroll
            for (int mt = 0; mt < 4; mt++)
                ldsm4(af[mt], aA + (unsigned)((wm + mt * 16 + a_row) * 144 + kk * 32 + a_koff));
#pragma unroll
            for (int np = 0; np < 4; np++) {
                unsigned r[4];
                ldsm4(r, aB + (unsigned)((wn + (np * 2 + b_blk) * 8 + b_row) * 144 + kk * 32 + b_koff));
                bf[np * 2][0] = r[0]; bf[np * 2][1] = r[1];
                bf[np * 2 + 1][0] = r[2]; bf[np * 2 + 1][1] = r[3];
            }
#pragma unroll
            for (int mt = 0; mt < 4; mt++)
#pragma unroll
                for (int nt = 0; nt < 8; nt++)
                    mma16(acc[mt][nt], af[mt], bf[nt]);
        }
    }

    // ---------------- epilogue ----------------
    const float Dscale = (EPI == 1) ? g_D * 256.f : 1.f;
#pragma unroll
    for (int mt = 0; mt < 4; mt++) {
#pragma unroll
        for (int nt = 0; nt < 8; nt++) {
            int cl = wn + nt * 8 + tg * 2;          // col in [0,128)
            int r0 = wm + mt * 16 + g;              // rows r0, r0+8
            float2 v01 = make_float2(acc[mt][nt][0], acc[mt][nt][1]);
            float2 v23 = make_float2(acc[mt][nt][2], acc[mt][nt][3]);
            if (EPI == 0) {
                float2 bb = *(const float2*)(bias + n0 + cl);
                v01.x = fmaxf(v01.x + bb.x, 0.f); v01.y = fmaxf(v01.y + bb.y, 0.f);
                v23.x = fmaxf(v23.x + bb.x, 0.f); v23.y = fmaxf(v23.y + bb.y, 0.f);
                int bx = blockIdx.x;                // 8 n-blocks of 128
                int lc = (bx & 1) * 128 + cl;       // col within 256-seg
                if (bx < 6) {                       // U/V/Z -> fp16 scratch
                    __half* dst = (bx < 2) ? g_Uh : ((bx < 4) ? g_Vh : g_Zh);
                    *(unsigned*)((char*)dst + ((size_t)(m0 + r0) * KC + lc) * 2) =
                        pack_h2(v01.x, v01.y);
                    *(unsigned*)((char*)dst + ((size_t)(m0 + r0 + 8) * KC + lc) * 2) =
                        pack_h2(v23.x, v23.y);
                } else {
                    *(float2*)(out + (size_t)(m0 + r0) * 512 + 256 + lc) = v01;
                    *(float2*)(out + (size_t)(m0 + r0 + 8) * 512 + 256 + lc) = v23;
                }
            } else {
                v01.x *= Dscale; v01.y *= Dscale; v23.x *= Dscale; v23.y *= Dscale;
                int gc = n0 + cl;
                *(float2*)(out + (size_t)(m0 + r0) * 512 + gc) = v01;
                *(float2*)(out + (size_t)(m0 + r0 + 8) * 512 + gc) = v23;
            }
        }
    }
}

// ======== fp16 TN GEMM (H partials): Hpart[z][j][k] = sum_nchunk Z[n,j]*V[n,k] ========
// 128 n-splits of 512 rows. Output tile 128(j) x 128(k), 8 warps, warp 64x32.
// Z,V fp16 stored [n][col]; fragments via ldmatrix.trans. 272B smem rows.
__global__ __launch_bounds__(256, 2)
void gemm_tn_h() {
    extern __shared__ unsigned smu[];
    const int RSu = 68;              // 272B rows
    const int TILE = 64 * RSu;       // 64 n-rows per operand, uints
    const int STu = 2 * TILE;

    int k0 = blockIdx.x * 128;       // V columns (H cols)
    int j0 = blockIdx.y * 128;       // Z columns (H rows)
    int nb = blockIdx.z * 512;       // n-chunk base
    int tid = threadIdx.x;
    int warp = tid >> 5, lane = tid & 31, g = lane >> 2, tg = lane & 3;
    int wm = (warp >> 2) * 64, wn = (warp & 3) * 32;

    float acc[4][4][4];
#pragma unroll
    for (int i = 0; i < 4; i++)
#pragma unroll
        for (int j = 0; j < 4; j++)
#pragma unroll
            for (int c = 0; c < 4; c++) acc[i][j][c] = 0.f;

    auto load_stage = [&](int s) {
        unsigned* sZ = smu + (s % 3) * STu;
        unsigned* sV = sZ + TILE;
        int r0 = nb + s * 64;
#pragma unroll
        for (int i = 0; i < 4; i++) {    // 64 rows x 128 halfs (16x16B/row) each
            int idx = tid + i * 256;
            int row = idx >> 4, q = idx & 15;
            cpa16(sZ + row * RSu + q * 4, g_Zh + (size_t)(r0 + row) * KC + j0 + q * 8);
            cpa16(sV + row * RSu + q * 4, g_Vh + (size_t)(r0 + row) * KC + k0 + q * 8);
        }
        cpcommit();
    };

    // trans-ldmatrix per-thread address components (reduction dim = n rows)
    const int a_n = (lane & 7) + 8 * ((lane >> 4) & 1);
    const int a_joff = 8 * ((lane >> 3) & 1);
    const int b_n = (lane & 7) + 8 * ((lane >> 3) & 1);

    const int NK = 8;                // 512 rows / 64
    load_stage(0);
    load_stage(1);

    for (int kt = 0; kt < NK; kt++) {
        if (kt + 1 < NK) cpwait<1>(); else cpwait<0>();
        __syncthreads();
        if (kt + 2 < NK) load_stage(kt + 2);

        const unsigned aZ = s2u(smu + (kt % 3) * STu);
        const unsigned aV = aZ + TILE * 4;

#pragma unroll
        for (int kk = 0; kk < 4; kk++) {     // 4 x 16-n mma steps per 64-n chunk
            unsigned af[4][4], bf[4][2];
#pragma unroll
            for (int mt = 0; mt < 4; mt++)
                ldsm4t(af[mt], aZ + (unsigned)((kk * 16 + a_n) * 272 + (wm + mt * 16 + a_joff) * 2));
#pragma unroll
            for (int nt = 0; nt < 4; nt++)
                ldsm2t(bf[nt], aV + (unsigned)((kk * 16 + b_n) * 272 + (wn + nt * 8) * 2));
#pragma unroll
            for (int mt = 0; mt < 4; mt++)
#pragma unroll
                for (int nt = 0; nt < 4; nt++)
                    mma16(acc[mt][nt], af[mt], bf[nt]);
        }
    }

    float* dst = g_Hpart + (size_t)blockIdx.z * (KC * KC);
#pragma unroll
    for (int mt = 0; mt < 4; mt++)
#pragma unroll
        for (int nt = 0; nt < 4; nt++)
#pragma unroll
            for (int c = 0; c < 4; c++) {
                int rl = wm + mt * 16 + g + ((c >= 2) ? 8 : 0);
                int cl = wn + nt * 8 + tg * 2 + (c & 1);
                dst[(j0 + rl) * KC + (k0 + cl)] = acc[mt][nt][c];
            }
}

// ---------------- column-sum partials (U, V fp16) ----------------
__global__ void colsum_k() {
    int j = threadIdx.x;
    int r0 = blockIdx.x * 256;
    const __half* src = (blockIdx.y == 0) ? g_Uh : g_Vh;
    float* dst = (blockIdx.y == 0) ? g_cspU : g_cspV;
    float s = 0.f;
    for (int r = 0; r < 256; r++) s += __half2float(src[(size_t)(r0 + r) * KC + j]);
    dst[blockIdx.x * KC + j] = s;
}

// ---------------- per-column dot partial: pdot[j] = su_j * sv_j ----------------
__global__ void sumpart_k() {
    int j = blockIdx.x;
    int t = threadIdx.x;
    float u = g_cspU[t * KC + j];
    float v = g_cspV[t * KC + j];
#pragma unroll
    for (int o = 16; o > 0; o >>= 1) {
        u += __shfl_xor_sync(0xffffffffu, u, o);
        v += __shfl_xor_sync(0xffffffffu, v, o);
    }
    __shared__ float ru[8], rv[8];
    if ((t & 31) == 0) { ru[t >> 5] = u; rv[t >> 5] = v; }
    __syncthreads();
    if (t == 0) {
        float su = 0.f, sv = 0.f;
        for (int w = 0; w < 8; w++) { su += ru[w]; sv += rv[w]; }
        g_pdot[j] = su * sv;
    }
}

// ---------------- scalar D ----------------
__global__ void scalar_k() {
    int t = threadIdx.x;
    float p = g_pdot[t * 8] + g_pdot[t * 8 + 1] + g_pdot[t * 8 + 2] + g_pdot[t * 8 + 3]
            + g_pdot[t * 8 + 4] + g_pdot[t * 8 + 5] + g_pdot[t * 8 + 6] + g_pdot[t * 8 + 7];
#pragma unroll
    for (int o = 16; o > 0; o >>= 1) p += __shfl_xor_sync(0xffffffffu, p, o);
    if (t == 0) g_D = 1.f / (p / (float)NROWS + 1e-6f);
}

// ---------------- reduce H partials -> fp16 H/256 ----------------
__global__ void reduceH_k() {
    int i = blockIdx.x * 256 + threadIdx.x;
    float s = 0.f;
    for (int p = 0; p < 128; p++) s += g_Hpart[(size_t)p * (KC * KC) + i];
    g_Hh[i] = __float2half_rn(s * (1.f / 256.f));
}

// ---------------- launcher ----------------
extern "C" void kernel_launch(void* const* d_in, const int* in_sizes, int n_in,
                              void* d_out, int out_size) {
    const float* x = (const float*)d_in[0];
    const float* W = (const float*)d_in[1];
    const float* b = (const float*)d_in[2];
    float* out = (float*)d_out;

    const int SM_H  = 3 * 2 * 128 * 36 * 4;   // 110592 B -> 2 CTAs/SM
    const int SM_TN = 3 * 2 * 64 * 68 * 4;    // 104448 B -> 2 CTAs/SM
    cudaFuncSetAttribute(gemm_h<1024, 0>, cudaFuncAttributeMaxDynamicSharedMemorySize, SM_H);
    cudaFuncSetAttribute(gemm_h<256, 1>,  cudaFuncAttributeMaxDynamicSharedMemorySize, SM_H);
    cudaFuncSetAttribute(gemm_tn_h,       cudaFuncAttributeMaxDynamicSharedMemorySize, SM_TN);

    // 0) prepasses + ncu alignment: gemm1 lands at global launch index 5 (-s 5)
    xh_k<<<NROWS * DDIM / 1024, 256>>>(x);
    Wh_k<<<1024, 256>>>(W);
    dummy_k<<<1, 32>>>();
    // 1) tmp = relu(x W^T + b): bx 0..5 -> Uh/Vh/Zh, 6..7 -> out[:,256:512]
    gemm_h<1024, 0><<<dim3(8, 512), 128, SM_H>>>(b, out);
    // 2) column sums of U and V (partials)
    colsum_k<<<dim3(256, 2), 256>>>();
    // 3) per-column dot partials
    sumpart_k<<<256, 256>>>();
    // 4) H = Z^T V partials over 128 n-splits (fp16, trans-ldmatrix)
    gemm_tn_h<<<dim3(2, 2, 128), 256, SM_TN>>>();
    // 5) D scalar
    scalar_k<<<1, 32>>>();
    // 6) reduce H partials -> fp16 H/256 (deterministic order)
    reduceH_k<<<128 * KC * KC / 0x7FFFFFFF ? 256 : 256, 256>>>();
    // 7) res = U * (H/256)^T * (D*256) -> out[:,0:256]
    gemm_h<256, 1><<<dim3(2, 512), 128, SM_H>>>(nullptr, out);
}

// round 16
// speedup vs baseline: 1.1755x; 1.0099x over previous
#include <cuda_runtime.h>
#include <cuda_fp16.h>
#include <cstdint>

// Problem constants
#define NROWS 65536
#define DDIM  1024
#define KC    256

// ---------------- device scratch (no allocations allowed) ----------------
__device__ __half g_xh[(size_t)NROWS * DDIM];  // rn-fp16 x
__device__ __half g_Uh[(size_t)NROWS * KC];    // rn-fp16 U
__device__ __half g_Vh[(size_t)NROWS * KC];    // rn-fp16 V
__device__ __half g_Zh[(size_t)NROWS * KC];    // rn-fp16 Z
__device__ __half g_Wh[(size_t)DDIM * DDIM];   // rn-fp16 W
__device__ __half g_Hh[KC * KC];               // rn-fp16 H/256
__device__ float  g_Hpart[32 * KC * KC];       // 32 n-splits of H = Z^T V
__device__ float  g_cspU[256 * KC];
__device__ float  g_cspV[256 * KC];
__device__ float  g_pdot[KC];
__device__ float  g_D;

// ---------------- helpers ----------------
// pack two f32 -> f16x2 (lo = first element, hi = second)
__device__ __forceinline__ unsigned pack_h2(float lo, float hi) {
    unsigned d;
    asm("cvt.rn.f16x2.f32 %0, %1, %2;" : "=r"(d) : "f"(hi), "f"(lo));
    return d;
}
__device__ __forceinline__ unsigned s2u(const void* p) {
    return (unsigned)__cvta_generic_to_shared(p);
}
__device__ __forceinline__ void cpa16(void* s, const void* g) {
    asm volatile("cp.async.cg.shared.global [%0], [%1], 16;" :: "r"(s2u(s)), "l"(g));
}
__device__ __forceinline__ void cpcommit() { asm volatile("cp.async.commit_group;"); }
template <int N> __device__ __forceinline__ void cpwait() {
    asm volatile("cp.async.wait_group %0;" :: "n"(N));
}
__device__ __forceinline__ void ldsm4(unsigned* r, unsigned a) {
    asm volatile("ldmatrix.sync.aligned.m8n8.x4.shared.b16 {%0,%1,%2,%3}, [%4];"
                 : "=r"(r[0]), "=r"(r[1]), "=r"(r[2]), "=r"(r[3]) : "r"(a));
}
__device__ __forceinline__ void ldsm4t(unsigned* r, unsigned a) {
    asm volatile("ldmatrix.sync.aligned.m8n8.x4.trans.shared.b16 {%0,%1,%2,%3}, [%4];"
                 : "=r"(r[0]), "=r"(r[1]), "=r"(r[2]), "=r"(r[3]) : "r"(a));
}
__device__ __forceinline__ void ldsm2t(unsigned* r, unsigned a) {
    asm volatile("ldmatrix.sync.aligned.m8n8.x2.trans.shared.b16 {%0,%1}, [%2];"
                 : "=r"(r[0]), "=r"(r[1]) : "r"(a));
}
__device__ __forceinline__ void mma16(float* c, const unsigned* a, const unsigned* b) {
    asm volatile(
        "mma.sync.aligned.m16n8k16.row.col.f32.f16.f16.f32 "
        "{%0,%1,%2,%3},{%4,%5,%6,%7},{%8,%9},{%0,%1,%2,%3};"
        : "+f"(c[0]), "+f"(c[1]), "+f"(c[2]), "+f"(c[3])
        : "r"(a[0]), "r"(a[1]), "r"(a[2]), "r"(a[3]), "r"(b[0]), "r"(b[1]));
}

// ---------------- prepasses ----------------
__global__ void xh_k(const float* __restrict__ x) {
    size_t i = ((size_t)blockIdx.x * 256 + threadIdx.x) * 4;
    float4 v = *(const float4*)(x + i);
    uint2 o;
    o.x = pack_h2(v.x, v.y);
    o.y = pack_h2(v.z, v.w);
    *(uint2*)((char*)g_xh + i * 2) = o;
}
__global__ void Wh_k(const float* __restrict__ W) {
    int i = (blockIdx.x * 256 + threadIdx.x) * 4;
    float4 v = *(const float4*)(W + i);
    uint2 o;
    o.x = pack_h2(v.x, v.y);
    o.y = pack_h2(v.z, v.w);
    *(uint2*)((char*)g_Wh + (size_t)i * 2) = o;
}
__global__ void dummy_k() {}

// ================= fp16 NT GEMM: C[M,N] = A[M,KA] * B[N,KA]^T =================
// CTA 128x128, 4 warps (2x2), warp tile 64x64. K-chunk 64 (4 x K16 mma).
// A,B fp16 smem, 144B rows (conflict-free ldmatrix), 3-stage cp.async,
// one __syncthreads per K-chunk, 2 CTAs/SM (110.6KB smem, 128 threads).
// EPI=0: bias+relu; bx 0..5 -> g_Uh/g_Vh/g_Zh (fp16), bx 6..7 -> out[:,256:512].
// EPI=1: res = U * (H/256)^T * (g_D*256) -> out[:, 0:256].
template <int KA, int EPI>
__global__ __launch_bounds__(128, 2)
void gemm_h(const float* __restrict__ bias, float* __restrict__ out) {
    extern __shared__ unsigned smu[];
    const int RS = 36;                       // row stride in uints (144B)
    const int TILE = 128 * RS;               // one operand tile, uints
    const int STu = 2 * TILE;                // stage size, uints

    const __half* A = (EPI == 1) ? g_Uh : g_xh;
    const __half* B = (EPI == 1) ? g_Hh : g_Wh;

    const int m0 = blockIdx.y * 128, n0 = blockIdx.x * 128;
    const int tid = threadIdx.x;
    const int warp = tid >> 5, lane = tid & 31, g = lane >> 2, tg = lane & 3;
    const int wm = (warp >> 1) * 64, wn = (warp & 1) * 64;

    float acc[4][8][4];
#pragma unroll
    for (int i = 0; i < 4; i++)
#pragma unroll
        for (int j = 0; j < 8; j++)
#pragma unroll
            for (int c = 0; c < 4; c++) acc[i][j][c] = 0.f;

    const int NK = KA / 64;

    auto load_stage = [&](int s) {
        unsigned* sA = smu + (s % 3) * STu;
        unsigned* sB = sA + TILE;
        const int k0 = s * 64;
#pragma unroll
        for (int i = 0; i < 8; i++) {        // A: 128 rows x 64 halfs (8x16B/row)
            int idx = tid + i * 128;
            int row = idx >> 3, q = idx & 7;
            cpa16(sA + row * RS + q * 4, A + (size_t)(m0 + row) * KA + k0 + q * 8);
        }
#pragma unroll
        for (int i = 0; i < 8; i++) {        // B: 128 rows x 64 halfs
            int idx = tid + i * 128;
            int row = idx >> 3, q = idx & 7;
            cpa16(sB + row * RS + q * 4, B + (size_t)(n0 + row) * KA + k0 + q * 8);
        }
        cpcommit();
    };

    // ldmatrix per-thread address components
    const int a_row = lane & 15;               // m row within 16
    const int a_koff = ((lane >> 4) & 1) * 16; // k half (bytes)
    const int b_row = lane & 7;                // n row within 8
    const int b_blk = (lane >> 4) & 1;         // which nt of the pair
    const int b_koff = ((lane >> 3) & 1) * 16; // k half (bytes)

    load_stage(0);
    load_stage(1);

    for (int kt = 0; kt < NK; kt++) {
        if (kt + 1 < NK) cpwait<1>(); else cpwait<0>();
        __syncthreads();
        // buffer (kt+2)%3 was last read in iter kt-1; readers passed the barrier.
        if (kt + 2 < NK) load_stage(kt + 2);

        const unsigned aA = s2u(smu + (kt % 3) * STu);
        const unsigned aB = aA + TILE * 4;

#pragma unroll
        for (int kk = 0; kk < 4; kk++) {     // 4 x K16 per K64 chunk
            unsigned af[4][4], bf[8][2];
#pragma unroll
            for (int mt = 0; mt < 4; mt++)
                ldsm4(af[mt], aA + (unsigned)((wm + mt * 16 + a_row) * 144 + kk * 32 + a_koff));
#pragma unroll
            for (int np = 0; np < 4; np++) {
                unsigned r[4];
                ldsm4(r, aB + (unsigned)((wn + (np * 2 + b_blk) * 8 + b_row) * 144 + kk * 32 + b_koff));
                bf[np * 2][0] = r[0]; bf[np * 2][1] = r[1];
                bf[np * 2 + 1][0] = r[2]; bf[np * 2 + 1][1] = r[3];
            }
#pragma unroll
            for (int mt = 0; mt < 4; mt++)
#pragma unroll
                for (int nt = 0; nt < 8; nt++)
                    mma16(acc[mt][nt], af[mt], bf[nt]);
        }
    }

    // ---------------- epilogue ----------------
    const float Dscale = (EPI == 1) ? g_D * 256.f : 1.f;
#pragma unroll
    for (int mt = 0; mt < 4; mt++) {
#pragma unroll
        for (int nt = 0; nt < 8; nt++) {
            int cl = wn + nt * 8 + tg * 2;          // col in [0,128)
            int r0 = wm + mt * 16 + g;              // rows r0, r0+8
            float2 v01 = make_float2(acc[mt][nt][0], acc[mt][nt][1]);
            float2 v23 = make_float2(acc[mt][nt][2], acc[mt][nt][3]);
            if (EPI == 0) {
                float2 bb = *(const float2*)(bias + n0 + cl);
                v01.x = fmaxf(v01.x + bb.x, 0.f); v01.y = fmaxf(v01.y + bb.y, 0.f);
                v23.x = fmaxf(v23.x + bb.x, 0.f); v23.y = fmaxf(v23.y + bb.y, 0.f);
                int bx = blockIdx.x;                // 8 n-blocks of 128
                int lc = (bx & 1) * 128 + cl;       // col within 256-seg
                if (bx < 6) {                       // U/V/Z -> fp16 scratch
                    __half* dst = (bx < 2) ? g_Uh : ((bx < 4) ? g_Vh : g_Zh);
                    *(unsigned*)((char*)dst + ((size_t)(m0 + r0) * KC + lc) * 2) =
                        pack_h2(v01.x, v01.y);
                    *(unsigned*)((char*)dst + ((size_t)(m0 + r0 + 8) * KC + lc) * 2) =
                        pack_h2(v23.x, v23.y);
                } else {
                    *(float2*)(out + (size_t)(m0 + r0) * 512 + 256 + lc) = v01;
                    *(float2*)(out + (size_t)(m0 + r0 + 8) * 512 + 256 + lc) = v23;
                }
            } else {
                v01.x *= Dscale; v01.y *= Dscale; v23.x *= Dscale; v23.y *= Dscale;
                int gc = n0 + cl;
                *(float2*)(out + (size_t)(m0 + r0) * 512 + gc) = v01;
                *(float2*)(out + (size_t)(m0 + r0 + 8) * 512 + gc) = v23;
            }
        }
    }
}

// ======== fp16 TN GEMM (H partials): Hpart[z][j][k] = sum_nchunk Z[n,j]*V[n,k] ========
// 32 n-splits of 2048 rows. Output tile 128(j) x 128(k), 8 warps, warp 64x32.
// Z,V fp16 stored [n][col]; fragments via ldmatrix.trans. 272B smem rows.
__global__ __launch_bounds__(256, 2)
void gemm_tn_h() {
    extern __shared__ unsigned smu[];
    const int RSu = 68;              // 272B rows
    const int TILE = 64 * RSu;       // 64 n-rows per operand, uints
    const int STu = 2 * TILE;

    int k0 = blockIdx.x * 128;       // V columns (H cols)
    int j0 = blockIdx.y * 128;       // Z columns (H rows)
    int nb = blockIdx.z * 2048;      // n-chunk base
    int tid = threadIdx.x;
    int warp = tid >> 5, lane = tid & 31, g = lane >> 2, tg = lane & 3;
    int wm = (warp >> 2) * 64, wn = (warp & 3) * 32;

    float acc[4][4][4];
#pragma unroll
    for (int i = 0; i < 4; i++)
#pragma unroll
        for (int j = 0; j < 4; j++)
#pragma unroll
            for (int c = 0; c < 4; c++) acc[i][j][c] = 0.f;

    auto load_stage = [&](int s) {
        unsigned* sZ = smu + (s % 3) * STu;
        unsigned* sV = sZ + TILE;
        int r0 = nb + s * 64;
#pragma unroll
        for (int i = 0; i < 4; i++) {    // 64 rows x 128 halfs (16x16B/row) each
            int idx = tid + i * 256;
            int row = idx >> 4, q = idx & 15;
            cpa16(sZ + row * RSu + q * 4, g_Zh + (size_t)(r0 + row) * KC + j0 + q * 8);
            cpa16(sV + row * RSu + q * 4, g_Vh + (size_t)(r0 + row) * KC + k0 + q * 8);
        }
        cpcommit();
    };

    // trans-ldmatrix per-thread address components (reduction dim = n rows)
    const int a_n = (lane & 7) + 8 * ((lane >> 4) & 1);
    const int a_joff = 8 * ((lane >> 3) & 1);
    const int b_n = (lane & 7) + 8 * ((lane >> 3) & 1);

    const int NK = 32;               // 2048 rows / 64
    load_stage(0);
    load_stage(1);

    for (int kt = 0; kt < NK; kt++) {
        if (kt + 1 < NK) cpwait<1>(); else cpwait<0>();
        __syncthreads();
        if (kt + 2 < NK) load_stage(kt + 2);

        const unsigned aZ = s2u(smu + (kt % 3) * STu);
        const unsigned aV = aZ + TILE * 4;

#pragma unroll
        for (int kk = 0; kk < 4; kk++) {     // 4 x 16-n mma steps per 64-n chunk
            unsigned af[4][4], bf[4][2];
#pragma unroll
            for (int mt = 0; mt < 4; mt++)
                ldsm4t(af[mt], aZ + (unsigned)((kk * 16 + a_n) * 272 + (wm + mt * 16 + a_joff) * 2));
#pragma unroll
            for (int nt = 0; nt < 4; nt++)
                ldsm2t(bf[nt], aV + (unsigned)((kk * 16 + b_n) * 272 + (wn + nt * 8) * 2));
#pragma unroll
            for (int mt = 0; mt < 4; mt++)
#pragma unroll
                for (int nt = 0; nt < 4; nt++)
                    mma16(acc[mt][nt], af[mt], bf[nt]);
        }
    }

    float* dst = g_Hpart + (size_t)blockIdx.z * (KC * KC);
#pragma unroll
    for (int mt = 0; mt < 4; mt++)
#pragma unroll
        for (int nt = 0; nt < 4; nt++)
#pragma unroll
            for (int c = 0; c < 4; c++) {
                int rl = wm + mt * 16 + g + ((c >= 2) ? 8 : 0);
                int cl = wn + nt * 8 + tg * 2 + (c & 1);
                dst[(j0 + rl) * KC + (k0 + cl)] = acc[mt][nt][c];
            }
}

// ---------------- column-sum partials (U, V fp16) ----------------
__global__ void colsum_k() {
    int j = threadIdx.x;
    int r0 = blockIdx.x * 256;
    const __half* src = (blockIdx.y == 0) ? g_Uh : g_Vh;
    float* dst = (blockIdx.y == 0) ? g_cspU : g_cspV;
    float s = 0.f;
    for (int r = 0; r < 256; r++) s += __half2float(src[(size_t)(r0 + r) * KC + j]);
    dst[blockIdx.x * KC + j] = s;
}

// ---------------- per-column dot partial: pdot[j] = su_j * sv_j ----------------
__global__ void sumpart_k() {
    int j = blockIdx.x;
    int t = threadIdx.x;
    float u = g_cspU[t * KC + j];
    float v = g_cspV[t * KC + j];
#pragma unroll
    for (int o = 16; o > 0; o >>= 1) {
        u += __shfl_xor_sync(0xffffffffu, u, o);
        v += __shfl_xor_sync(0xffffffffu, v, o);
    }
    __shared__ float ru[8], rv[8];
    if ((t & 31) == 0) { ru[t >> 5] = u; rv[t >> 5] = v; }
    __syncthreads();
    if (t == 0) {
        float su = 0.f, sv = 0.f;
        for (int w = 0; w < 8; w++) { su += ru[w]; sv += rv[w]; }
        g_pdot[j] = su * sv;
    }
}

// ---------------- scalar D ----------------
__global__ void scalar_k() {
    int t = threadIdx.x;
    float p = g_pdot[t * 8] + g_pdot[t * 8 + 1] + g_pdot[t * 8 + 2] + g_pdot[t * 8 + 3]
            + g_pdot[t * 8 + 4] + g_pdot[t * 8 + 5] + g_pdot[t * 8 + 6] + g_pdot[t * 8 + 7];
#pragma unroll
    for (int o = 16; o > 0; o >>= 1) p += __shfl_xor_sync(0xffffffffu, p, o);
    if (t == 0) g_D = 1.f / (p / (float)NROWS + 1e-6f);
}

// ---------------- reduce H partials -> fp16 H/256 ----------------
__global__ void reduceH_k() {
    int i = blockIdx.x * 256 + threadIdx.x;
    float s = 0.f;
    for (int p = 0; p < 32; p++) s += g_Hpart[(size_t)p * (KC * KC) + i];
    g_Hh[i] = __float2half_rn(s * (1.f / 256.f));
}

// ---------------- launcher ----------------
extern "C" void kernel_launch(void* const* d_in, const int* in_sizes, int n_in,
                              void* d_out, int out_size) {
    const float* x = (const float*)d_in[0];
    const float* W = (const float*)d_in[1];
    const float* b = (const float*)d_in[2];
    float* out = (float*)d_out;

    const int SM_H  = 3 * 2 * 128 * 36 * 4;   // 110592 B -> 2 CTAs/SM
    const int SM_TN = 3 * 2 * 64 * 68 * 4;    // 104448 B -> 2 CTAs/SM
    cudaFuncSetAttribute(gemm_h<1024, 0>, cudaFuncAttributeMaxDynamicSharedMemorySize, SM_H);
    cudaFuncSetAttribute(gemm_h<256, 1>,  cudaFuncAttributeMaxDynamicSharedMemorySize, SM_H);
    cudaFuncSetAttribute(gemm_tn_h,       cudaFuncAttributeMaxDynamicSharedMemorySize, SM_TN);

    // 0) prepasses + ncu alignment: gemm1 lands at global launch index 5 (-s 5)
    xh_k<<<NROWS * DDIM / 1024, 256>>>(x);
    Wh_k<<<1024, 256>>>(W);
    dummy_k<<<1, 32>>>();
    // 1) tmp = relu(x W^T + b): bx 0..5 -> Uh/Vh/Zh, 6..7 -> out[:,256:512]
    gemm_h<1024, 0><<<dim3(8, 512), 128, SM_H>>>(b, out);
    // 2) column sums of U and V (partials)
    colsum_k<<<dim3(256, 2), 256>>>();
    // 3) per-column dot partials
    sumpart_k<<<256, 256>>>();
    // 4) H = Z^T V partials over 32 n-splits (fp16, trans-ldmatrix, 1 wave)
    gemm_tn_h<<<dim3(2, 2, 32), 256, SM_TN>>>();
    // 5) D scalar
    scalar_k<<<1, 32>>>();
    // 6) reduce H partials -> fp16 H/256 (deterministic order)
    reduceH_k<<<256, 256>>>();
    // 7) res = U * (H/256)^T * (D*256) -> out[:,0:256]
    gemm_h<256, 1><<<dim3(2, 512), 128, SM_H>>>(nullptr, out);
}